// round 17
// baseline (speedup 1.0000x reference)
#include <cuda_runtime.h>
#include <cuda_fp16.h>
#include <math.h>
#include <stdint.h>

#define D_MODEL   768
#define D_STATE   64
#define D_CONV    4
#define HEADDIM   64
#define D_INNER   1536
#define NHEADS    24
#define CONV_DIM  1664
#define D_IN_PROJ 3224
#define BATCH     2
#define SEQLEN    4096
#define ROWS      (BATCH*SEQLEN)
#define NPAD1     3328
#define NCHUNK    64
#define CT        64

// ---------------- scratch (device globals; no allocation) ----------------
__device__ __half g_zxbcdt[(size_t)ROWS * D_IN_PROJ];
__device__ __half g_xBC[(size_t)ROWS * CONV_DIM];
__device__ __half g_yraw[(size_t)ROWS * D_INNER];
__device__ float g_dtT[(size_t)BATCH * NHEADS * SEQLEN];
__device__ float g_dtAT[(size_t)BATCH * NHEADS * SEQLEN];
__device__ __half g_S[(size_t)BATCH * NHEADS * NCHUNK * HEADDIM * D_STATE];
__device__ __half g_H[(size_t)BATCH * NHEADS * NCHUNK * HEADDIM * D_STATE];
__device__ float g_P[(size_t)BATCH * NHEADS * NCHUNK];
__device__ __half g_xh[(size_t)ROWS * D_MODEL];
__device__ __half g_yh[(size_t)ROWS * D_INNER];
__device__ __half g_wi[(size_t)NPAD1 * D_MODEL];
__device__ __half g_wo[(size_t)D_MODEL * D_INNER];

// ---------------- common PTX helpers ----------------
__device__ __forceinline__ void cp16(uint32_t dst, const void* src) {
    asm volatile("cp.async.ca.shared.global [%0], [%1], 16;" :: "r"(dst), "l"(src) : "memory");
}
__device__ __forceinline__ void cp_commit() {
    asm volatile("cp.async.commit_group;" ::: "memory");
}
template <int N> __device__ __forceinline__ void cp_wait() {
    asm volatile("cp.async.wait_group %0;" :: "n"(N) : "memory");
}
__device__ __forceinline__ void ldsm4(uint32_t* r, uint32_t addr) {
    asm volatile("ldmatrix.sync.aligned.m8n8.x4.shared.b16 {%0,%1,%2,%3}, [%4];"
                 : "=r"(r[0]), "=r"(r[1]), "=r"(r[2]), "=r"(r[3]) : "r"(addr));
}
__device__ __forceinline__ void mma_f16(float* d, const uint32_t* a, uint32_t b0, uint32_t b1) {
    asm volatile("mma.sync.aligned.m16n8k16.row.col.f32.f16.f16.f32 "
                 "{%0,%1,%2,%3}, {%4,%5,%6,%7}, {%8,%9}, {%0,%1,%2,%3};"
                 : "+f"(d[0]), "+f"(d[1]), "+f"(d[2]), "+f"(d[3])
                 : "r"(a[0]), "r"(a[1]), "r"(a[2]), "r"(a[3]), "r"(b0), "r"(b1));
}

// ---------------- warp-MMA fp16 GEMM (KC=32, 2 CTA/SM), ldc-aware ----------------
#define KC      32
#define PITCH   40
#define TILE_E  (128 * PITCH)
#define TILE_B  (TILE_E * 2)
#define STAGE_B (2 * TILE_B)
#define STAGES  3
#define GSMEM   (STAGES * STAGE_B)      // 61440 bytes

template <typename TOUT>
__global__ void __launch_bounds__(256, 2) mma_gemm(
    const __half* __restrict__ Ah, const __half* __restrict__ Bh,
    TOUT* __restrict__ C, int M, int N, int K, int ldc) {
    extern __shared__ __half sm[];
    const int tid = threadIdx.x;
    const int wid = tid >> 5, lane = tid & 31;
    const int warp_m = wid >> 1, warp_n = wid & 1;
    const int g = lane >> 2, tig = lane & 3;
    const int bm = blockIdx.y * 128, bn = blockIdx.x * 128;
    const uint32_t sbase = (uint32_t)__cvta_generic_to_shared(sm);

    float acc[2][8][4];
#pragma unroll
    for (int mt = 0; mt < 2; mt++)
#pragma unroll
        for (int nt = 0; nt < 8; nt++)
#pragma unroll
            for (int i = 0; i < 4; i++) acc[mt][nt][i] = 0.f;

    const int nkt = K / KC;
    const int r_ld = tid >> 2, seg_ld = tid & 3;

    auto issue = [&](int kt) {
        const int st = kt % STAGES;
        const int kofs = kt * KC;
        const uint32_t dst0 = sbase + st * STAGE_B;
        const __half* srcs[2] = {Ah, Bh};
#pragma unroll
        for (int arr = 0; arr < 2; arr++) {
            const int rbase = (arr == 0) ? bm : bn;
            const uint32_t db = dst0 + arr * TILE_B;
#pragma unroll
            for (int i = 0; i < 2; i++) {
                const int r = r_ld + i * 64;
                cp16(db + (uint32_t)(r * PITCH + seg_ld * 8) * 2,
                     srcs[arr] + (size_t)(rbase + r) * K + kofs + seg_ld * 8);
            }
        }
    };

    issue(0); cp_commit();
    if (nkt > 1) { issue(1); cp_commit(); }

    const int a_row = (lane & 15);
    const int a_col = (lane >> 4) * 8;
    const int b_row = (lane & 7) + ((lane >> 4) * 8);
    const int b_col = ((lane >> 3) & 1) * 8;

    for (int kt = 0; kt < nkt; kt++) {
        if (kt + 2 < nkt) cp_wait<1>(); else cp_wait<0>();
        __syncthreads();
        if (kt + 2 < nkt) { issue(kt + 2); cp_commit(); }

        const uint32_t st0 = sbase + (kt % STAGES) * STAGE_B;
        const uint32_t aA = st0;
        const uint32_t bB = st0 + TILE_B;

#pragma unroll
        for (int ks = 0; ks < KC; ks += 16) {
            uint32_t ah[2][4], bf[4][4];
#pragma unroll
            for (int mt = 0; mt < 2; mt++) {
                const uint32_t aoff =
                    (uint32_t)((warp_m * 32 + mt * 16 + a_row) * PITCH + ks + a_col) * 2;
                ldsm4(ah[mt], aA + aoff);
            }
#pragma unroll
            for (int ntp = 0; ntp < 4; ntp++) {
                const uint32_t boff =
                    (uint32_t)((warp_n * 64 + ntp * 16 + b_row) * PITCH + ks + b_col) * 2;
                ldsm4(bf[ntp], bB + boff);
            }
#pragma unroll
            for (int nt = 0; nt < 8; nt++) {
                const uint32_t b0 = bf[nt >> 1][(nt & 1) * 2];
                const uint32_t b1 = bf[nt >> 1][(nt & 1) * 2 + 1];
#pragma unroll
                for (int mt = 0; mt < 2; mt++)
                    mma_f16(acc[mt][nt], ah[mt], b0, b1);
            }
        }
        __syncthreads();
    }

#pragma unroll
    for (int mt = 0; mt < 2; mt++) {
        const int row0 = bm + warp_m * 32 + mt * 16 + g;
#pragma unroll
        for (int nt = 0; nt < 8; nt++) {
            const int col = bn + warp_n * 64 + nt * 8 + 2 * tig;
            if (col < N) {
                if constexpr (sizeof(TOUT) == 4) {
                    *(float2*)&C[(size_t)row0 * ldc + col] =
                        make_float2(acc[mt][nt][0], acc[mt][nt][1]);
                    *(float2*)&C[(size_t)(row0 + 8) * ldc + col] =
                        make_float2(acc[mt][nt][2], acc[mt][nt][3]);
                } else {
                    *(__half2*)&C[(size_t)row0 * ldc + col] = __halves2half2(
                        __float2half(acc[mt][nt][0]), __float2half(acc[mt][nt][1]));
                    *(__half2*)&C[(size_t)(row0 + 8) * ldc + col] = __halves2half2(
                        __float2half(acc[mt][nt][2]), __float2half(acc[mt][nt][3]));
                }
            }
        }
    }
}

// ---------------- fp32 -> fp16 convert ----------------
__global__ void convert_f16(const float* __restrict__ src,
                            __half* __restrict__ dst, int n4) {
    int i = blockIdx.x * blockDim.x + threadIdx.x;
    if (i >= n4) return;
    const int idx = i * 4;
    float4 v = *(const float4*)(src + idx);
    __half h[4];
    h[0] = __float2half(v.x); h[1] = __float2half(v.y);
    h[2] = __float2half(v.z); h[3] = __float2half(v.w);
    *(uint2*)(dst + idx) = *(uint2*)h;
}

// ---------------- transpose to fp16 ----------------
__global__ void transpose_f16(const float* __restrict__ src,
                              __half* __restrict__ dst,
                              int R, int C, int Cpad) {
    __shared__ float tile[32][33];
    const int c0 = blockIdx.x * 32, r0 = blockIdx.y * 32;
    const int tx = threadIdx.x, ty = threadIdx.y;
    const int c = c0 + tx;
#pragma unroll
    for (int j = ty; j < 32; j += 8) {
        const int r = r0 + j;
        tile[j][tx] = (r < R && c < C) ? src[(size_t)r * C + c] : 0.f;
    }
    __syncthreads();
#pragma unroll
    for (int j = ty; j < 32; j += 8) {
        const int orow = c0 + j;
        const int ocol = r0 + tx;
        if (orow < Cpad && ocol < R)
            dst[(size_t)orow * R + ocol] = __float2half(tile[tx][j]);
    }
}

// ---------------- dt (reads fp16 zxbcdt; col >= D_INNER -> GEMM1a stripe) --------
__global__ void dt_kernel(const float* __restrict__ dt_bias,
                          const float* __restrict__ A_log) {
    int idx = blockIdx.x * blockDim.x + threadIdx.x;
    if (idx >= BATCH * NHEADS * SEQLEN) return;
    const int l = idx % SEQLEN;
    const int bh = idx / SEQLEN;
    const int h = bh % NHEADS, b = bh / NHEADS;
    float v = __half2float(
                  g_zxbcdt[(size_t)(b * SEQLEN + l) * D_IN_PROJ + (D_INNER + CONV_DIM) + h])
              + dt_bias[h];
    float dtv = (v > 20.f) ? v : log1pf(expf(v));
    float A = -expf(A_log[h]);
    g_dtT[idx] = dtv;
    g_dtAT[idx] = dtv * A;
}

// ---------------- causal depthwise conv + silu (fp16 in/out) ----------------
#define NC4 (CONV_DIM / 4)
__global__ void conv_kernel(const float* __restrict__ conv_w,
                            const float* __restrict__ conv_b) {
    int i = blockIdx.x * blockDim.x + threadIdx.x;
    if (i >= (ROWS / 4) * NC4) return;
    const int c4 = (i % NC4) * 4;
    const int rb = (i / NC4) * 4;
    const int l0 = rb & (SEQLEN - 1);

    const float4 bias = *(const float4*)(conv_b + c4);
    const float4 w0 = *(const float4*)(conv_w + (c4 + 0) * 4);
    const float4 w1 = *(const float4*)(conv_w + (c4 + 1) * 4);
    const float4 w2 = *(const float4*)(conv_w + (c4 + 2) * 4);
    const float4 w3 = *(const float4*)(conv_w + (c4 + 3) * 4);
    const float wt0[4] = {w0.x, w0.y, w0.z, w0.w};
    const float wt1[4] = {w1.x, w1.y, w1.z, w1.w};
    const float wt2[4] = {w2.x, w2.y, w2.z, w2.w};
    const float wt3[4] = {w3.x, w3.y, w3.z, w3.w};

    float4 v[7];
#pragma unroll
    for (int j = 0; j < 7; j++) {
        const int ls = l0 + j - 3;
        if (ls >= 0) {
            uint2 raw = *(const uint2*)(g_zxbcdt +
                (size_t)(rb + j - 3) * D_IN_PROJ + D_INNER + c4);
            const __half* h4 = (const __half*)&raw;
            v[j] = make_float4(__half2float(h4[0]), __half2float(h4[1]),
                               __half2float(h4[2]), __half2float(h4[3]));
        } else {
            v[j] = make_float4(0.f, 0.f, 0.f, 0.f);
        }
    }

#pragma unroll
    for (int j = 0; j < 4; j++) {
        float4 acc = bias;
#pragma unroll
        for (int k = 0; k < D_CONV; k++) {
            acc.x += v[j + k].x * wt0[k];
            acc.y += v[j + k].y * wt1[k];
            acc.z += v[j + k].z * wt2[k];
            acc.w += v[j + k].w * wt3[k];
        }
        __half h[4];
        h[0] = __float2half(acc.x / (1.f + expf(-acc.x)));
        h[1] = __float2half(acc.y / (1.f + expf(-acc.y)));
        h[2] = __float2half(acc.z / (1.f + expf(-acc.z)));
        h[3] = __float2half(acc.w / (1.f + expf(-acc.w)));
        *(uint2*)(g_xBC + (size_t)(rb + j) * CONV_DIM + c4) = *(uint2*)h;
    }
}

// ================= chunked SSM scan (tensor-core) =================
#define SPITCH 72

// Phase A: A = w*x (fp32 -> hi/lo), B pure fp16. 2 MMAs per tile.
__global__ void __launch_bounds__(256) chunk_state(void) {
    __shared__ __half sAh[CT * SPITCH], sAl[CT * SPITCH];
    __shared__ __half sBh[CT * SPITCH];
    __shared__ float sL[CT], sdt[CT];
    const int c = blockIdx.x, h = blockIdx.y, b = blockIdx.z;
    const int tid = threadIdx.x;
    const int bh = b * NHEADS + h;
    const int rowbase = b * SEQLEN + c * CT;

    if (tid < CT) {
        sdt[tid] = g_dtT[(size_t)bh * SEQLEN + c * CT + tid];
        sL[tid]  = g_dtAT[(size_t)bh * SEQLEN + c * CT + tid];
    }
    __syncthreads();
    if (tid == 0) {
        float run = 0.f;
        for (int t = 0; t < CT; t++) { run += sL[t]; sL[t] = run; }
    }
    __syncthreads();
    const float Lend = sL[CT - 1];

    for (int e = tid; e < CT * 16; e += 256) {
        const int t = e >> 4, q = e & 15;
        const __half* rowp = g_xBC + (size_t)(rowbase + t) * CONV_DIM;
        const float w = sdt[t] * expf(Lend - sL[t]);
        uint2 xr = *(const uint2*)(rowp + h * HEADDIM + q * 4);
        uint2 br = *(const uint2*)(rowp + D_INNER + q * 4);
        const __half* x4 = (const __half*)&xr;
        const __half* b4 = (const __half*)&br;
#pragma unroll
        for (int j = 0; j < 4; j++) {
            const int p = q * 4 + j;
            const float xa = __half2float(x4[j]) * w;
            __half hx = __float2half(xa);
            sAh[p * SPITCH + t] = hx;
            sAl[p * SPITCH + t] = __float2half(xa - __half2float(hx));
            sBh[p * SPITCH + t] = b4[j];
        }
    }
    __syncthreads();

    const int wid = tid >> 5, lane = tid & 31;
    const int warp_m = wid & 3, warp_n = wid >> 2;
    const int a_row = lane & 15, a_col = (lane >> 4) * 8;
    const int b_row = (lane & 7) + ((lane >> 4) * 8), b_col = ((lane >> 3) & 1) * 8;
    const uint32_t uAh = (uint32_t)__cvta_generic_to_shared(sAh);
    const uint32_t uAl = (uint32_t)__cvta_generic_to_shared(sAl);
    const uint32_t uBh = (uint32_t)__cvta_generic_to_shared(sBh);

    float acc[4][4];
#pragma unroll
    for (int nt = 0; nt < 4; nt++)
#pragma unroll
        for (int i = 0; i < 4; i++) acc[nt][i] = 0.f;

#pragma unroll
    for (int kt = 0; kt < 4; kt++) {
        const int k0 = kt * 16;
        uint32_t ah[4], al[4], bh[2][4];
        const uint32_t aoff = (uint32_t)((warp_m * 16 + a_row) * SPITCH + k0 + a_col) * 2;
        ldsm4(ah, uAh + aoff);
        ldsm4(al, uAl + aoff);
#pragma unroll
        for (int nb = 0; nb < 2; nb++) {
            const uint32_t boff =
                (uint32_t)((warp_n * 32 + nb * 16 + b_row) * SPITCH + k0 + b_col) * 2;
            ldsm4(bh[nb], uBh + boff);
        }
#pragma unroll
        for (int nt = 0; nt < 4; nt++) {
            const int nb = nt >> 1, pr = (nt & 1) * 2;
            mma_f16(acc[nt], ah, bh[nb][pr], bh[nb][pr + 1]);
            mma_f16(acc[nt], al, bh[nb][pr], bh[nb][pr + 1]);
        }
    }

    __half* Sb = g_S + ((size_t)bh * NCHUNK + c) * (HEADDIM * D_STATE);
    const int g = lane >> 2, tig = lane & 3;
#pragma unroll
    for (int nt = 0; nt < 4; nt++) {
        const int ncol = warp_n * 32 + nt * 8 + 2 * tig;
        const int prow = warp_m * 16 + g;
        *(__half2*)&Sb[prow * D_STATE + ncol] =
            __halves2half2(__float2half(acc[nt][0]), __float2half(acc[nt][1]));
        *(__half2*)&Sb[(prow + 8) * D_STATE + ncol] =
            __halves2half2(__float2half(acc[nt][2]), __float2half(acc[nt][3]));
    }
    if (tid == 0) g_P[(size_t)bh * NCHUNK + c] = Lend;
}

// Phase B: fully parallel over state elements; S,H fp16
#define SPB 16
__global__ void __launch_bounds__(256) state_pass(void) {
    const int blk = blockIdx.x;
    const int bh = blk / SPB, seg = blk % SPB;
    const int e = seg * 256 + threadIdx.x;
    __shared__ float sP[NCHUNK];
    if (threadIdx.x < NCHUNK)
        sP[threadIdx.x] = expf(g_P[(size_t)bh * NCHUNK + threadIdx.x]);
    __syncthreads();
    float hv = 0.f;
    const size_t base = (size_t)bh * NCHUNK * (HEADDIM * D_STATE) + e;
#pragma unroll 4
    for (int c = 0; c < NCHUNK; c++) {
        const size_t off = base + (size_t)c * (HEADDIM * D_STATE);
        g_H[off] = __float2half(hv);
        hv = sP[c] * hv + __half2float(g_S[off]);
    }
}

// Phase C: pure-fp16 C/B/X/H -> 6 smem tiles, 4 MMAs per tile
#define CTILE (CT * SPITCH)
#define CSMEM (6 * CTILE * 2 + 2 * CT * 4)
__global__ void __launch_bounds__(256) chunk_output(const float* __restrict__ Dparam) {
    extern __shared__ __half cs[];
    __half* sCh = cs;
    __half* sB2h = cs + CTILE;
    __half* sXh = cs + 2 * CTILE;
    __half* sHh = cs + 3 * CTILE;
    __half* sGh = cs + 4 * CTILE;
    __half* sGl = cs + 5 * CTILE;
    float* sL = (float*)(cs + 6 * CTILE);
    float* sdt = sL + CT;

    const int c = blockIdx.x, h = blockIdx.y, b = blockIdx.z;
    const int tid = threadIdx.x;
    const int bh = b * NHEADS + h;
    const int rowbase = b * SEQLEN + c * CT;
    const float Dh = Dparam[h];

    if (tid < CT) {
        sdt[tid] = g_dtT[(size_t)bh * SEQLEN + c * CT + tid];
        sL[tid]  = g_dtAT[(size_t)bh * SEQLEN + c * CT + tid];
    }
    __syncthreads();
    if (tid == 0) {
        float run = 0.f;
        for (int t = 0; t < CT; t++) { run += sL[t]; sL[t] = run; }
    }

    const __half* Hbase = g_H + ((size_t)bh * NCHUNK + c) * (HEADDIM * D_STATE);
    for (int e = tid; e < CT * 16; e += 256) {
        const int t = e >> 4, q = e & 15;
        const __half* rowp = g_xBC + (size_t)(rowbase + t) * CONV_DIM;
        uint2 cr = *(const uint2*)(rowp + D_INNER + D_STATE + q * 4);
        uint2 br = *(const uint2*)(rowp + D_INNER + q * 4);
        uint2 xr = *(const uint2*)(rowp + h * HEADDIM + q * 4);
        uint2 hr = *(const uint2*)(Hbase + t * D_STATE + q * 4);
        const __half* c4 = (const __half*)&cr;
        const __half* b4 = (const __half*)&br;
        const __half* x4 = (const __half*)&xr;
        const __half* h4 = (const __half*)&hr;
#pragma unroll
        for (int j = 0; j < 4; j++) {
            const int n = q * 4 + j;
            sCh[t * SPITCH + n] = c4[j];
            sB2h[t * SPITCH + n] = b4[j];
            sXh[n * SPITCH + t] = x4[j];
            sHh[t * SPITCH + n] = h4[j];
        }
    }
    __syncthreads();

    const int wid = tid >> 5, lane = tid & 31;
    const int warp_m = wid & 3, warp_n = wid >> 2;
    const int a_row = lane & 15, a_col = (lane >> 4) * 8;
    const int b_row = (lane & 7) + ((lane >> 4) * 8), b_col = ((lane >> 3) & 1) * 8;
    const int g = lane >> 2, tig = lane & 3;
    const uint32_t uCh = (uint32_t)__cvta_generic_to_shared(sCh);
    const uint32_t uB2h = (uint32_t)__cvta_generic_to_shared(sB2h);
    const uint32_t uXh = (uint32_t)__cvta_generic_to_shared(sXh);
    const uint32_t uHh = (uint32_t)__cvta_generic_to_shared(sHh);
    const uint32_t uGh = (uint32_t)__cvta_generic_to_shared(sGh);
    const uint32_t uGl = (uint32_t)__cvta_generic_to_shared(sGl);

    float gacc[4][4];
#pragma unroll
    for (int nt = 0; nt < 4; nt++)
#pragma unroll
        for (int i = 0; i < 4; i++) gacc[nt][i] = 0.f;
#pragma unroll
    for (int kt = 0; kt < 4; kt++) {
        const int k0 = kt * 16;
        uint32_t ah[4], bh[2][4];
        const uint32_t aoff = (uint32_t)((warp_m * 16 + a_row) * SPITCH + k0 + a_col) * 2;
        ldsm4(ah, uCh + aoff);
#pragma unroll
        for (int nb = 0; nb < 2; nb++) {
            const uint32_t boff =
                (uint32_t)((warp_n * 32 + nb * 16 + b_row) * SPITCH + k0 + b_col) * 2;
            ldsm4(bh[nb], uB2h + boff);
        }
#pragma unroll
        for (int nt = 0; nt < 4; nt++) {
            const int nb = nt >> 1, pr = (nt & 1) * 2;
            mma_f16(gacc[nt], ah, bh[nb][pr], bh[nb][pr + 1]);
        }
    }
    __syncthreads();

#pragma unroll
    for (int nt = 0; nt < 4; nt++) {
        const int s0 = warp_n * 32 + nt * 8 + 2 * tig;
#pragma unroll
        for (int r = 0; r < 2; r++) {
            const int t = warp_m * 16 + g + r * 8;
            float v0 = gacc[nt][r * 2], v1 = gacc[nt][r * 2 + 1];
            const float Lt = sL[t];
            v0 = (s0 <= t)     ? v0 * sdt[s0]     * expf(Lt - sL[s0])     : 0.f;
            v1 = (s0 + 1 <= t) ? v1 * sdt[s0 + 1] * expf(Lt - sL[s0 + 1]) : 0.f;
            __half h0 = __float2half(v0), h1 = __float2half(v1);
            *(__half2*)&sGh[t * SPITCH + s0] = __halves2half2(h0, h1);
            *(__half2*)&sGl[t * SPITCH + s0] = __halves2half2(
                __float2half(v0 - __half2float(h0)), __float2half(v1 - __half2float(h1)));
        }
    }
    __syncthreads();

    float yacc[4][4], cacc[4][4];
#pragma unroll
    for (int nt = 0; nt < 4; nt++)
#pragma unroll
        for (int i = 0; i < 4; i++) { yacc[nt][i] = 0.f; cacc[nt][i] = 0.f; }
#pragma unroll
    for (int kt = 0; kt < 4; kt++) {
        const int k0 = kt * 16;
        uint32_t gh[4], gl[4], ch[4];
        uint32_t xh[2][4], hh[2][4];
        const uint32_t aoff = (uint32_t)((warp_m * 16 + a_row) * SPITCH + k0 + a_col) * 2;
        ldsm4(gh, uGh + aoff);
        ldsm4(gl, uGl + aoff);
        ldsm4(ch, uCh + aoff);
#pragma unroll
        for (int nb = 0; nb < 2; nb++) {
            const uint32_t boff =
                (uint32_t)((warp_n * 32 + nb * 16 + b_row) * SPITCH + k0 + b_col) * 2;
            ldsm4(xh[nb], uXh + boff);
            ldsm4(hh[nb], uHh + boff);
        }
#pragma unroll
        for (int nt = 0; nt < 4; nt++) {
            const int nb = nt >> 1, pr = (nt & 1) * 2;
            mma_f16(yacc[nt], gh, xh[nb][pr], xh[nb][pr + 1]);
            mma_f16(yacc[nt], gl, xh[nb][pr], xh[nb][pr + 1]);
            mma_f16(cacc[nt], ch, hh[nb][pr], hh[nb][pr + 1]);
        }
    }

#pragma unroll
    for (int nt = 0; nt < 4; nt++) {
        const int p = warp_n * 32 + nt * 8 + 2 * tig;
#pragma unroll
        for (int r = 0; r < 2; r++) {
            const int t = warp_m * 16 + g + r * 8;
            const float et = expf(sL[t]);
            const float x0 = __half2float(sXh[p * SPITCH + t]);
            const float x1 = __half2float(sXh[(p + 1) * SPITCH + t]);
            const float o0 = yacc[nt][r * 2] + cacc[nt][r * 2] * et + Dh * x0;
            const float o1 = yacc[nt][r * 2 + 1] + cacc[nt][r * 2 + 1] * et + Dh * x1;
            *(__half2*)&g_yraw[(size_t)(rowbase + t) * D_INNER + h * HEADDIM + p] =
                __halves2half2(__float2half(o0), __float2half(o1));
        }
    }
}

// ---------------- gate + RMSNorm (z fp16 in, y fp16 in), writing fp16 ----------------
__global__ void __launch_bounds__(192) norm_kernel(const float* __restrict__ norm_w) {
    const int row = blockIdx.x;
    const int tid = threadIdx.x;
    const __half* zrow = g_zxbcdt + (size_t)row * D_IN_PROJ;
    const __half* yrow = g_yraw + (size_t)row * D_INNER;
    __half* hrow = g_yh + (size_t)row * D_INNER;

    float4 gv[2];
    float ss = 0.f;
#pragma unroll
    for (int i = 0; i < 2; i++) {
        const int idx = tid + i * 192;
        uint2 zr = *(const uint2*)(zrow + idx * 4);
        uint2 yr = *(const uint2*)(yrow + idx * 4);
        const __half* z4 = (const __half*)&zr;
        const __half* y4 = (const __half*)&yr;
        float4 y;
        {
            const float z0 = __half2float(z4[0]), z1 = __half2float(z4[1]);
            const float z2 = __half2float(z4[2]), z3 = __half2float(z4[3]);
            y.x = __half2float(y4[0]) * (z0 / (1.f + expf(-z0)));
            y.y = __half2float(y4[1]) * (z1 / (1.f + expf(-z1)));
            y.z = __half2float(y4[2]) * (z2 / (1.f + expf(-z2)));
            y.w = __half2float(y4[3]) * (z3 / (1.f + expf(-z3)));
        }
        gv[i] = y;
        ss += y.x * y.x + y.y * y.y + y.z * y.z + y.w * y.w;
    }
#pragma unroll
    for (int o = 16; o; o >>= 1) ss += __shfl_xor_sync(0xffffffffu, ss, o);
    __shared__ float red[6];
    if ((tid & 31) == 0) red[tid >> 5] = ss;
    __syncthreads();
    __shared__ float stotal;
    if (tid == 0) {
        float v = red[0] + red[1] + red[2] + red[3] + red[4] + red[5];
        stotal = rsqrtf(v * (1.f / D_INNER) + 1e-5f);
    }
    __syncthreads();
    const float scale = stotal;
#pragma unroll
    for (int i = 0; i < 2; i++) {
        const int idx = tid + i * 192;
        float4 w = *(const float4*)(norm_w + idx * 4);
        __half h[4];
        h[0] = __float2half(gv[i].x * scale * w.x);
        h[1] = __float2half(gv[i].y * scale * w.y);
        h[2] = __float2half(gv[i].z * scale * w.z);
        h[3] = __float2half(gv[i].w * scale * w.w);
        *(uint2*)(hrow + idx * 4) = *(uint2*)h;
    }
}

// ---------------- launch ----------------
#define N_XBCDT (D_IN_PROJ - D_INNER)    // 1688 (pads to 1792 = 14 tiles)
extern "C" void kernel_launch(void* const* d_in, const int* in_sizes, int n_in,
                              void* d_out, int out_size) {
    const float* x       = (const float*)d_in[0];
    const float* W_in    = (const float*)d_in[1];
    const float* conv_w  = (const float*)d_in[2];
    const float* conv_b  = (const float*)d_in[3];
    const float* dt_bias = (const float*)d_in[4];
    const float* A_log   = (const float*)d_in[5];
    const float* Dp      = (const float*)d_in[6];
    const float* norm_w  = (const float*)d_in[7];
    const float* W_out   = (const float*)d_in[8];
    float* out = (float*)d_out;

    __half *zx_ptr, *xh, *yh, *wi, *wo;
    cudaGetSymbolAddress((void**)&zx_ptr, g_zxbcdt);
    cudaGetSymbolAddress((void**)&xh, g_xh);
    cudaGetSymbolAddress((void**)&yh, g_yh);
    cudaGetSymbolAddress((void**)&wi, g_wi);
    cudaGetSymbolAddress((void**)&wo, g_wo);

    static cudaStream_t s1;
    static cudaEvent_t evA, evB, evC, evE;
    static int attr_set = 0;
    if (!attr_set) {
        cudaFuncSetAttribute(mma_gemm<__half>, cudaFuncAttributeMaxDynamicSharedMemorySize, GSMEM);
        cudaFuncSetAttribute(mma_gemm<float>, cudaFuncAttributeMaxDynamicSharedMemorySize, GSMEM);
        cudaFuncSetAttribute(chunk_output, cudaFuncAttributeMaxDynamicSharedMemorySize, CSMEM);
        cudaStreamCreateWithFlags(&s1, cudaStreamNonBlocking);
        cudaEventCreateWithFlags(&evA, cudaEventDisableTiming);
        cudaEventCreateWithFlags(&evB, cudaEventDisableTiming);
        cudaEventCreateWithFlags(&evC, cudaEventDisableTiming);
        cudaEventCreateWithFlags(&evE, cudaEventDisableTiming);
        attr_set = 1;
    }

    // ---- fork 1: weight transposes on s1 concurrent with x convert ----
    cudaEventRecord(evA, 0);
    cudaStreamWaitEvent(s1, evA, 0);
    transpose_f16<<<dim3(NPAD1 / 32, D_MODEL / 32), dim3(32, 8), 0, s1>>>(
        W_in, wi, D_MODEL, D_IN_PROJ, NPAD1);
    transpose_f16<<<dim3(D_MODEL / 32, D_INNER / 32), dim3(32, 8), 0, s1>>>(
        W_out, wo, D_INNER, D_MODEL, D_MODEL);
    convert_f16<<<(ROWS * D_MODEL / 4 + 255) / 256, 256>>>(x, xh, ROWS * D_MODEL / 4);
    cudaEventRecord(evB, s1);
    cudaStreamWaitEvent(0, evB, 0);

    // GEMM1a: xBC+dt stripe (cols D_INNER..D_IN_PROJ) on main stream
    mma_gemm<__half><<<dim3((N_XBCDT + 127) / 128, ROWS / 128), 256, GSMEM>>>(
        xh, wi + (size_t)D_INNER * D_MODEL, zx_ptr + D_INNER,
        ROWS, N_XBCDT, D_MODEL, D_IN_PROJ);

    // ---- fork 2: GEMM1b (z stripe) on s1, overlapping the conv+chunk chain ----
    cudaEventRecord(evC, 0);
    cudaStreamWaitEvent(s1, evC, 0);
    mma_gemm<__half><<<dim3(D_INNER / 128, ROWS / 128), 256, GSMEM, s1>>>(
        xh, wi, zx_ptr, ROWS, D_INNER, D_MODEL, D_IN_PROJ);
    cudaEventRecord(evE, s1);

    // main chain (depends only on GEMM1a)
    dt_kernel<<<(BATCH * NHEADS * SEQLEN + 255) / 256, 256>>>(dt_bias, A_log);
    conv_kernel<<<((ROWS / 4) * NC4 + 255) / 256, 256>>>(conv_w, conv_b);
    chunk_state<<<dim3(NCHUNK, NHEADS, BATCH), 256>>>();
    state_pass<<<BATCH * NHEADS * SPB, 256>>>();
    chunk_output<<<dim3(NCHUNK, NHEADS, BATCH), 256, CSMEM>>>(Dp);

    // join z-stripe before norm
    cudaStreamWaitEvent(0, evE, 0);
    norm_kernel<<<ROWS, 192>>>(norm_w);

    // GEMM2: out = y @ W_out (fp32 output)
    mma_gemm<float><<<dim3(D_MODEL / 128, ROWS / 128), 256, GSMEM>>>(
        yh, wo, out, ROWS, D_MODEL, D_INNER, D_MODEL);
}